// round 1
// baseline (speedup 1.0000x reference)
#include <cuda_runtime.h>

#define TT 8
#define NSUB 20000
#define MSUB 5000
#define HD 128
#define NNZG 200000
#define NNZE 100000
#define ITEM_NUM 40000
#define USER_NUM 10000

// ---------------- scratch (static device globals; no runtime alloc) --------
__device__ float g_X[(long)TT * NSUB * HD];   // 81.92 MB
__device__ float g_Y[(long)TT * NSUB * HD];   // 81.92 MB

__device__ int   g_cnt[TT * NSUB];
__device__ int   g_ptrA[TT * (NSUB + 1)];
__device__ int   g_posA[TT * NSUB];
__device__ int   g_ci[TT * NNZG];
__device__ float g_cvv[TT * NNZG];

__device__ int   e_cnt[TT * MSUB];
__device__ int   e_ptrA[TT * (MSUB + 1)];
__device__ int   e_posA[TT * MSUB];
__device__ int   e_ci[TT * NNZE];
__device__ float e_cvv[TT * NNZE];

// ---------------- CSR build --------------------------------------------------
__global__ void zero_cnt_kernel() {
    int i = blockIdx.x * blockDim.x + threadIdx.x;
    if (i < TT * NSUB) g_cnt[i] = 0;
    if (i < TT * MSUB) e_cnt[i] = 0;
}

__global__ void hist_kernel(const int* __restrict__ rows, int* __restrict__ cnt,
                            int nnz, int nrows) {
    int i = blockIdx.x * blockDim.x + threadIdx.x;
    if (i >= TT * nnz) return;
    int t = i / nnz;
    atomicAdd(&cnt[t * nrows + rows[i]], 1);
}

// one block (1024 thr) per t: exclusive scan of cnt -> ptr (and pos copy)
__global__ void scan_kernel(const int* __restrict__ cnt, int* __restrict__ ptr,
                            int* __restrict__ pos, int n) {
    int t = blockIdx.x;
    cnt += t * n; ptr += t * (n + 1); pos += t * n;
    __shared__ int sh[1024];
    __shared__ int carry;
    if (threadIdx.x == 0) carry = 0;
    __syncthreads();
    for (int base = 0; base < n; base += 1024) {
        int i = base + threadIdx.x;
        int v = (i < n) ? cnt[i] : 0;
        sh[threadIdx.x] = v;
        __syncthreads();
        for (int off = 1; off < 1024; off <<= 1) {
            int add = (threadIdx.x >= off) ? sh[threadIdx.x - off] : 0;
            __syncthreads();
            sh[threadIdx.x] += add;
            __syncthreads();
        }
        int excl = carry + sh[threadIdx.x] - v;
        if (i < n) { ptr[i] = excl; pos[i] = excl; }
        __syncthreads();
        if (threadIdx.x == 1023) carry += sh[1023];
        __syncthreads();
    }
    if (threadIdx.x == 0) ptr[n] = carry;
}

__global__ void scatter_kernel(const int* __restrict__ rows, const int* __restrict__ cols,
                               const float* __restrict__ vals, int* __restrict__ pos,
                               int* __restrict__ ci, float* __restrict__ cv,
                               int nnz, int nrows) {
    int i = blockIdx.x * blockDim.x + threadIdx.x;
    if (i >= TT * nnz) return;
    int t = i / nnz;
    int r = rows[i];
    int p = atomicAdd(&pos[t * nrows + r], 1);
    ci[(long)t * nnz + p] = cols[i];
    cv[(long)t * nnz + p] = vals[i];
}

// ---------------- SpMM: one warp per output row ------------------------------
__global__ void spmm_kernel(const int* __restrict__ ptr, const int* __restrict__ ci,
                            const float* __restrict__ cv,
                            const float* __restrict__ xb, long xts,
                            float* __restrict__ yb, long yts,
                            int rows_per_t, int nnz, int do_relu) {
    int w = (blockIdx.x * blockDim.x + threadIdx.x) >> 5;
    int lane = threadIdx.x & 31;
    if (w >= TT * rows_per_t) return;
    int t = w / rows_per_t;
    int r = w - t * rows_per_t;
    const int* pp = ptr + t * (rows_per_t + 1);
    int jb = pp[r], je = pp[r + 1];
    const float4* x4 = (const float4*)(xb + (long)t * xts);
    const int*   cit = ci + (long)t * nnz;
    const float* cvt = cv + (long)t * nnz;
    float4 acc = make_float4(0.f, 0.f, 0.f, 0.f);
    for (int j0 = jb; j0 < je; j0 += 32) {
        int myc = 0; float myv = 0.f;
        if (j0 + lane < je) { myc = cit[j0 + lane]; myv = cvt[j0 + lane]; }
        int m = min(32, je - j0);
        for (int q = 0; q < m; q++) {
            int   c = __shfl_sync(0xffffffffu, myc, q);
            float v = __shfl_sync(0xffffffffu, myv, q);
            float4 g = x4[c * 32 + lane];
            acc.x += v * g.x; acc.y += v * g.y; acc.z += v * g.z; acc.w += v * g.w;
        }
    }
    if (do_relu) {
        acc.x = fmaxf(acc.x, 0.f); acc.y = fmaxf(acc.y, 0.f);
        acc.z = fmaxf(acc.z, 0.f); acc.w = fmaxf(acc.w, 0.f);
    }
    ((float4*)(yb + (long)t * yts))[r * 32 + lane] = acc;
}

// ---------------- gated fusion: x = sig(x0 W+b)*x0 + sig(x1 W+b)*x1 ---------
// CTA: 32 rows of one t; dyn smem: W[128x128] + X0t[128][36] + X1t[128][36]
#define GATE_SMEM ((16384 + 2 * 128 * 36) * 4)
__global__ __launch_bounds__(256) void gate_kernel(
    const float* __restrict__ item_base, const float* __restrict__ dy_tab,
    const float* __restrict__ Wg, const float* __restrict__ bg,
    const int* __restrict__ rev_i, const int* __restrict__ rev_lat) {
    extern __shared__ float sm[];
    float* Ws = sm;
    float* X0 = sm + 16384;
    float* X1 = X0 + 128 * 36;
    int t = blockIdx.y;
    int m0 = blockIdx.x * 32;
    int tid = threadIdx.x;

    const float4* wsrc = (const float4*)(Wg + (long)t * 16384);
    float4* wdst = (float4*)Ws;
    for (int i = tid; i < 4096; i += 256) wdst[i] = wsrc[i];

    {
        int r = tid >> 3, sub = tid & 7;
        int i0 = rev_i[t * NSUB + m0 + r];
        int i1 = rev_lat[t * NSUB + m0 + r];
        const float4* a = (const float4*)(item_base + (long)i0 * HD);
        const float4* b = (const float4*)(dy_tab + (long)i1 * HD);
#pragma unroll
        for (int q = 0; q < 4; q++) {
            int k4 = sub + q * 8, k = k4 * 4;
            float4 v = a[k4];
            X0[(k + 0) * 36 + r] = v.x; X0[(k + 1) * 36 + r] = v.y;
            X0[(k + 2) * 36 + r] = v.z; X0[(k + 3) * 36 + r] = v.w;
            float4 u = b[k4];
            X1[(k + 0) * 36 + r] = u.x; X1[(k + 1) * 36 + r] = u.y;
            X1[(k + 2) * 36 + r] = u.z; X1[(k + 3) * 36 + r] = u.w;
        }
    }
    __syncthreads();

    int cx = tid & 31, ry = tid >> 5, r0 = ry * 4;
    float acc0[4][4] = {}, acc1[4][4] = {};
#pragma unroll 4
    for (int k = 0; k < 128; k++) {
        const float* wr = &Ws[k * 128 + cx];
        float w[4]; w[0] = wr[0]; w[1] = wr[32]; w[2] = wr[64]; w[3] = wr[96];
        float4 xa = *(const float4*)&X0[k * 36 + r0];
        float4 xb = *(const float4*)&X1[k * 36 + r0];
        float a[4] = {xa.x, xa.y, xa.z, xa.w};
        float b[4] = {xb.x, xb.y, xb.z, xb.w};
#pragma unroll
        for (int i = 0; i < 4; i++)
#pragma unroll
            for (int j = 0; j < 4; j++) {
                acc0[i][j] += a[i] * w[j];
                acc1[i][j] += b[i] * w[j];
            }
    }

    float bv[4];
#pragma unroll
    for (int j = 0; j < 4; j++) bv[j] = bg[t * 128 + cx + 32 * j];
#pragma unroll
    for (int i = 0; i < 4; i++) {
        int r = r0 + i;
        long orow = ((long)t * NSUB + m0 + r) * HD;
#pragma unroll
        for (int j = 0; j < 4; j++) {
            int c = cx + 32 * j;
            float s0 = 1.f / (1.f + __expf(-(acc0[i][j] + bv[j])));
            float s1 = 1.f / (1.f + __expf(-(acc1[i][j] + bv[j])));
            g_X[orow + c] = s0 * X0[c * 36 + r] + s1 * X1[c * 36 + r];
        }
    }
}

// ---------------- dense layer GEMM: Y = X @ W[t,l] + b[t,l] -----------------
// CTA: 64 rows; dyn smem: W[128x128] + Xt[128][68]
#define GEMM_SMEM ((16384 + 128 * 68) * 4)
__global__ __launch_bounds__(256) void hgnn_gemm(
    const float* __restrict__ Wh, const float* __restrict__ bh, int l) {
    extern __shared__ float sm[];
    float* Ws = sm;
    float* Xs = sm + 16384;
    int t = blockIdx.y;
    int m0 = blockIdx.x * 64;
    int tid = threadIdx.x;

    const float4* wsrc = (const float4*)(Wh + ((long)t * 2 + l) * 16384);
    float4* wdst = (float4*)Ws;
    for (int i = tid; i < 4096; i += 256) wdst[i] = wsrc[i];

    {
        int r = tid >> 2, sub = tid & 3;
        int row = m0 + r;
        bool ok = row < NSUB;
        const float4* a = (const float4*)(g_X + ((long)t * NSUB + (ok ? row : 0)) * HD);
#pragma unroll
        for (int q = 0; q < 8; q++) {
            int k4 = sub + q * 4, k = k4 * 4;
            float4 v = ok ? a[k4] : make_float4(0.f, 0.f, 0.f, 0.f);
            Xs[(k + 0) * 68 + r] = v.x; Xs[(k + 1) * 68 + r] = v.y;
            Xs[(k + 2) * 68 + r] = v.z; Xs[(k + 3) * 68 + r] = v.w;
        }
    }
    __syncthreads();

    int cx = tid & 31, ry = tid >> 5, r0 = ry * 8;
    float acc[8][4] = {};
#pragma unroll 2
    for (int k = 0; k < 128; k++) {
        const float* wr = &Ws[k * 128 + cx];
        float w[4]; w[0] = wr[0]; w[1] = wr[32]; w[2] = wr[64]; w[3] = wr[96];
        float4 xa = *(const float4*)&Xs[k * 68 + r0];
        float4 xb = *(const float4*)&Xs[k * 68 + r0 + 4];
        float a[8] = {xa.x, xa.y, xa.z, xa.w, xb.x, xb.y, xb.z, xb.w};
#pragma unroll
        for (int i = 0; i < 8; i++)
#pragma unroll
            for (int j = 0; j < 4; j++) acc[i][j] += a[i] * w[j];
    }

    float bv[4];
#pragma unroll
    for (int j = 0; j < 4; j++) bv[j] = bh[((long)t * 2 + l) * 128 + cx + 32 * j];
#pragma unroll
    for (int i = 0; i < 8; i++) {
        int row = m0 + r0 + i;
        if (row < NSUB) {
            float* yr = &g_Y[((long)t * NSUB + row) * HD + cx];
#pragma unroll
            for (int j = 0; j < 4; j++) yr[32 * j] = acc[i][j] + bv[j];
        }
    }
}

// ---------------- host ------------------------------------------------------
static void* sym_addr_i(const int* sym)    { void* p = 0; cudaGetSymbolAddress(&p, (const void*)sym); return p; }
static void* sym_addr_f(const float* sym)  { void* p = 0; cudaGetSymbolAddress(&p, (const void*)sym); return p; }

extern "C" void kernel_launch(void* const* d_in, const int* in_sizes, int n_in,
                              void* d_out, int out_size) {
    const float* item_base = (const float*)d_in[0];
    const float* user_base = (const float*)d_in[1];
    const float* dy_tab    = (const float*)d_in[2];
    const float* Wg        = (const float*)d_in[3];
    const float* bg        = (const float*)d_in[4];
    const float* Wh        = (const float*)d_in[5];
    const float* bh        = (const float*)d_in[6];
    const float* gv        = (const float*)d_in[7];
    const float* ev        = (const float*)d_in[8];
    const int*   rev_i     = (const int*)d_in[9];
    const int*   rev_lat   = (const int*)d_in[10];
    const int*   grows     = (const int*)d_in[11];
    const int*   gcols     = (const int*)d_in[12];
    const int*   erows     = (const int*)d_in[13];
    const int*   ecols     = (const int*)d_in[14];
    float* out = (float*)d_out;

    cudaFuncSetAttribute(gate_kernel, cudaFuncAttributeMaxDynamicSharedMemorySize, GATE_SMEM);
    cudaFuncSetAttribute(hgnn_gemm,   cudaFuncAttributeMaxDynamicSharedMemorySize, GEMM_SMEM);

    // base tables -> output
    cudaMemcpyAsync(out, user_base, (size_t)USER_NUM * HD * sizeof(float),
                    cudaMemcpyDeviceToDevice, 0);
    cudaMemcpyAsync(out + (size_t)(USER_NUM + TT * MSUB) * HD, item_base,
                    (size_t)ITEM_NUM * HD * sizeof(float), cudaMemcpyDeviceToDevice, 0);

    // CSR build for G and E
    int* d_gcnt = (int*)sym_addr_i(g_cnt);
    int* d_gptr = (int*)sym_addr_i(g_ptrA);
    int* d_gpos = (int*)sym_addr_i(g_posA);
    int* d_gci  = (int*)sym_addr_i(g_ci);
    float* d_gcv = (float*)sym_addr_f(g_cvv);
    int* d_ecnt = (int*)sym_addr_i(e_cnt);
    int* d_eptr = (int*)sym_addr_i(e_ptrA);
    int* d_epos = (int*)sym_addr_i(e_posA);
    int* d_eci  = (int*)sym_addr_i(e_ci);
    float* d_ecv = (float*)sym_addr_f(e_cvv);
    float* d_X = (float*)sym_addr_f(g_X);
    float* d_Y = (float*)sym_addr_f(g_Y);

    zero_cnt_kernel<<<(TT * NSUB + 255) / 256, 256>>>();
    hist_kernel<<<(TT * NNZG + 255) / 256, 256>>>(grows, d_gcnt, NNZG, NSUB);
    hist_kernel<<<(TT * NNZE + 255) / 256, 256>>>(erows, d_ecnt, NNZE, MSUB);
    scan_kernel<<<TT, 1024>>>(d_gcnt, d_gptr, d_gpos, NSUB);
    scan_kernel<<<TT, 1024>>>(d_ecnt, d_eptr, d_epos, MSUB);
    scatter_kernel<<<(TT * NNZG + 255) / 256, 256>>>(grows, gcols, gv, d_gpos, d_gci, d_gcv, NNZG, NSUB);
    scatter_kernel<<<(TT * NNZE + 255) / 256, 256>>>(erows, ecols, ev, d_epos, d_eci, d_ecv, NNZE, MSUB);

    // gated fusion -> g_X
    {
        dim3 grid(NSUB / 32, TT);
        gate_kernel<<<grid, 256, GATE_SMEM>>>(item_base, dy_tab, Wg, bg, rev_i, rev_lat);
    }

    float* out_item = out + (size_t)(USER_NUM + TT * MSUB + ITEM_NUM) * HD; // row 90000
    float* out_user = out + (size_t)USER_NUM * HD;                          // row 10000

    // layer 0: GEMM then SpMM(relu) back into g_X
    {
        dim3 grid((NSUB + 63) / 64, TT);
        hgnn_gemm<<<grid, 256, GEMM_SMEM>>>(Wh, bh, 0);
        spmm_kernel<<<(TT * NSUB * 32) / 256, 256>>>(d_gptr, d_gci, d_gcv,
            d_Y, (long)NSUB * HD, d_X, (long)NSUB * HD, NSUB, NNZG, 1);
    }
    // layer 1: GEMM then SpMM(relu) directly into output item area
    {
        dim3 grid((NSUB + 63) / 64, TT);
        hgnn_gemm<<<grid, 256, GEMM_SMEM>>>(Wh, bh, 1);
        spmm_kernel<<<(TT * NSUB * 32) / 256, 256>>>(d_gptr, d_gci, d_gcv,
            d_Y, (long)NSUB * HD, out_item, (long)NSUB * HD, NSUB, NNZG, 1);
    }
    // edge aggregation: E @ x -> user area
    spmm_kernel<<<(TT * MSUB * 32) / 256, 256>>>(d_eptr, d_eci, d_ecv,
        out_item, (long)NSUB * HD, out_user, (long)MSUB * HD, MSUB, NNZE, 0);
}